// round 5
// baseline (speedup 1.0000x reference)
#include <cuda_runtime.h>

#define Np 1024
#define HW 4096
#define NBLK 1024       // stripe blocks
#define RPB  4          // rows per block (NBLK*RPB == HW)

// ---------------- scratch -------------------------------------------------
__device__ double   g_part[(size_t)Np * NBLK];   // 8 MB per-(box,stripe) partials
__device__ float    g_scores[Np];
__device__ float    g_scores_s[Np];
__device__ float    g_bbox_s[Np * 4];
__device__ unsigned g_iou[Np * 32];
__device__ float    g_rec_score[Np];
__device__ unsigned g_rec_sel[Np * 32];

// ---------------- K1: fused stripe scan + per-box row-interval sums --------
// 1024 blocks x 4 rows. Per row: store 16-elt LOCAL inclusive scans + a
// 256-entry chunk-exclusive array; C[x] = sExcl[x>>4] + sLoc[x]. No
// add-back pass. Identical arithmetic to materializing the full prefix.
__global__ void k_boxsum(const float4* __restrict__ p,
                         const float* __restrict__ bbox) {
    __shared__ float srow[HW];      // local scans
    __shared__ float sExcl[256];    // per-chunk exclusive prefix
    __shared__ float swsum[8];
    int t = threadIdx.x;            // 256
    int lane = t & 31, wid = t >> 5;
    int blk = blockIdx.x;

    int bx1[4], bx2[4], by1[4], by2[4];
    double acc[4] = {0.0, 0.0, 0.0, 0.0};
#pragma unroll
    for (int k = 0; k < 4; k++) {
        int b = t + k * 256;
        float4 bb = reinterpret_cast<const float4*>(bbox)[b];
        bx1[k] = min(max((int)floorf(bb.x), 0), HW);
        by1[k] = min(max((int)floorf(bb.y), 0), HW);
        bx2[k] = min(max((int)floorf(bb.z), 0), HW);
        by2[k] = min(max((int)floorf(bb.w), 0), HW);
    }

    int y0 = blk * RPB;
#pragma unroll
    for (int r = 0; r < RPB; r++) {
        int y = y0 + r;
        const float4* pr = p + (size_t)y * (HW / 4);
        float4 v0 = pr[t * 4 + 0], v1 = pr[t * 4 + 1];
        float4 v2 = pr[t * 4 + 2], v3 = pr[t * 4 + 3];
        // local inclusive scan of 16 elements
        v0.y += v0.x; v0.z += v0.y; v0.w += v0.z;
        v1.x += v0.w; v1.y += v1.x; v1.z += v1.y; v1.w += v1.z;
        v2.x += v1.w; v2.y += v2.x; v2.z += v2.y; v2.w += v2.z;
        v3.x += v2.w; v3.y += v3.x; v3.z += v3.y; v3.w += v3.z;
        float tot = v3.w;
        // store local scans immediately (independent of warp scan)
        float4* sr4 = reinterpret_cast<float4*>(srow);
        sr4[t * 4 + 0] = v0; sr4[t * 4 + 1] = v1;
        sr4[t * 4 + 2] = v2; sr4[t * 4 + 3] = v3;
        // warp inclusive scan of per-thread totals
        float ts = tot;
#pragma unroll
        for (int o = 1; o < 32; o <<= 1) {
            float u = __shfl_up_sync(0xffffffffu, ts, o);
            if (lane >= o) ts += u;
        }
        if (lane == 31) swsum[wid] = ts;
        __syncthreads();
        float w = 0.f;
#pragma unroll
        for (int q = 0; q < 8; q++)
            if (q < wid) w += swsum[q];
        sExcl[t] = w + (ts - tot);
        __syncthreads();
#pragma unroll
        for (int k = 0; k < 4; k++) {
            if (y >= by1[k] && y < by2[k]) {
                int xr = bx2[k] - 1, xl = bx1[k] - 1;
                float right = (bx2[k] > 0) ? (sExcl[xr >> 4] + srow[xr]) : 0.f;
                float left  = (bx1[k] > 0) ? (sExcl[xl >> 4] + srow[xl]) : 0.f;
                acc[k] += (double)(right - left);
            }
        }
        __syncthreads();  // protect srow/sExcl/swsum before next row
    }
#pragma unroll
    for (int k = 0; k < 4; k++) {
        int b = t + k * 256;
        g_part[(size_t)b * NBLK + blk] = acc[k];
    }
}

// ---------------- K2: reduce partials -> combined score --------------------
__global__ void k_boxscore(const float* __restrict__ bbox,
                           const float* __restrict__ obj) {
    int gw   = (blockIdx.x * blockDim.x + threadIdx.x) >> 5;
    int lane = threadIdx.x & 31;
    if (gw >= Np) return;
    const double* part = g_part + (size_t)gw * NBLK;
    double s = 0.0;
#pragma unroll
    for (int q = 0; q < NBLK / 32; q++) s += part[lane + q * 32];
#pragma unroll
    for (int o = 16; o > 0; o >>= 1) s += __shfl_down_sync(0xffffffffu, s, o);
    if (lane == 0) {
        float4 b = reinterpret_cast<const float4*>(bbox)[gw];
        int x1 = min(max((int)floorf(b.x), 0), HW);
        int y1 = min(max((int)floorf(b.y), 0), HW);
        int x2 = min(max((int)floorf(b.z), 0), HW);
        int y2 = min(max((int)floorf(b.w), 0), HW);
        long long cnt = (long long)(y2 - y1) * (long long)(x2 - x1);
        if (cnt < 1) cnt = 1;
        float bs = (float)(s / (double)cnt);
        g_scores[gw] = 0.5f * (obj[gw] + bs);
    }
}

// ---------------- K3: rank sort (desc score, ties asc index == stable) -----
__global__ void k_sort(const float* __restrict__ bbox) {
    __shared__ float ss[Np];
    int t = threadIdx.x;  // 256
    for (int k = t; k < Np; k += 256) ss[k] = g_scores[k];
    __syncthreads();
    int i    = blockIdx.x * 8 + (t >> 5);
    int lane = t & 31;
    float si = ss[i];
    int cnt = 0;
#pragma unroll
    for (int q = 0; q < 32; q++) {
        int j = q * 32 + lane;
        float sj = ss[j];
        cnt += (sj > si) || (sj == si && j < i);
    }
#pragma unroll
    for (int o = 16; o > 0; o >>= 1) cnt += __shfl_down_sync(0xffffffffu, cnt, o);
    if (lane == 0) {
        g_scores_s[cnt] = si;
        reinterpret_cast<float4*>(g_bbox_s)[cnt] =
            reinterpret_cast<const float4*>(bbox)[i];
    }
}

// ---------------- K4: IoU bitmask — one warp per 8 output words ------------
__global__ void k_iou() {
    int g    = (blockIdx.x * blockDim.x + threadIdx.x) >> 5;  // 0..4095
    int lane = threadIdx.x & 31;
    int i    = g >> 2;
    int wb   = (g & 3) * 8;
    float4 a = reinterpret_cast<const float4*>(g_bbox_s)[i];
    float aarea = (a.z - a.x) * (a.w - a.y);
    unsigned myw = 0;
#pragma unroll
    for (int w = 0; w < 8; w++) {
        int j = (wb + w) * 32 + lane;
        float4 c = reinterpret_cast<const float4*>(g_bbox_s)[j];
        float carea = (c.z - c.x) * (c.w - c.y);
        float ix1 = fmaxf(a.x, c.x), iy1 = fmaxf(a.y, c.y);
        float ix2 = fminf(a.z, c.z), iy2 = fminf(a.w, c.w);
        float iw = fmaxf(ix2 - ix1, 0.f), ih = fmaxf(iy2 - iy1, 0.f);
        float inter = iw * ih;
        float iou = inter / (aarea + carea - inter);
        unsigned b = __ballot_sync(0xffffffffu, iou > 0.5f);
        if (lane == w) myw = b;
    }
    if (lane < 8) g_iou[i * 32 + wb + lane] = myw;
}

// ---------------- K5: c_wsl greedy sweep — one warp per start --------------
// Prefetched row; record-check moved to the add site: size hits counts at
// iter j0 -> reference records at top of iter j0+1 iff j0+1 <= Np-1.
__global__ void k_cwsl(const int* __restrict__ counts_p) {
    int gw   = (blockIdx.x * blockDim.x + threadIdx.x) >> 5;
    int lane = threadIdx.x & 31;
    if (gw >= Np) return;
    int counts = counts_p[0];
    int i = gw;
    unsigned sel = (lane == (i >> 5)) ? (1u << (i & 31)) : 0u;
    int   size  = 1;
    float score = g_scores_s[i];
    bool  rec   = false;
    if (size == counts) {
        rec = (i < Np - 1);
    } else {
        unsigned row = (i + 1 < Np) ? g_iou[(i + 1) * 32 + lane] : 0u;
        for (int j = i + 1; j < Np; j++) {
            unsigned nxt = (j + 1 < Np) ? g_iou[(j + 1) * 32 + lane] : 0u;
            bool overlap = __any_sync(0xffffffffu, (sel & row) != 0u);
            if (!overlap) {
                if (lane == (j >> 5)) sel |= (1u << (j & 31));
                size++;
                score += g_scores_s[j];
                if (size == counts) { rec = (j < Np - 1); break; }
            }
            row = nxt;
        }
    }
    g_rec_sel[i * 32 + lane] = sel;
    if (lane == 0) g_rec_score[i] = rec ? score : -1e30f;
}

// ---------------- K6: last-argmax over recorded scores + emit output -------
__global__ void k_final(float* __restrict__ out) {
    __shared__ float ss[Np];
    __shared__ int   si[Np];
    int t = threadIdx.x;
    ss[t] = g_rec_score[t];
    si[t] = t;
    __syncthreads();
    for (int s = Np / 2; s > 0; s >>= 1) {
        if (t < s) {
            float o = ss[t + s]; int oi = si[t + s];
            if (o > ss[t] || (o == ss[t] && oi > si[t])) { ss[t] = o; si[t] = oi; }
        }
        __syncthreads();
    }
    __shared__ int bestIdx, anyrec;
    if (t == 0) { bestIdx = si[0]; anyrec = (ss[0] > -1e29f) ? 1 : 0; }
    __syncthreads();
    unsigned bit = (g_rec_sel[bestIdx * 32 + (t >> 5)] >> (t & 31)) & 1u;
    out[t] = (anyrec && bit) ? g_scores_s[t] : 0.f;
}

// ---------------- launch ----------------------------------------------------
extern "C" void kernel_launch(void* const* d_in, const int* in_sizes, int n_in,
                              void* d_out, int out_size) {
    const float* bbox   = (const float*)d_in[0];
    const float* obj    = (const float*)d_in[1];
    const float* probs  = (const float*)d_in[2];
    const int*   counts = (const int*)d_in[3];
    float* out = (float*)d_out;

    k_boxsum<<<NBLK, 256>>>((const float4*)probs, bbox);
    k_boxscore<<<(Np * 32) / 256, 256>>>(bbox, obj);
    k_sort<<<Np / 8, 256>>>(bbox);
    k_iou<<<(Np * 32 * 32 / 8) / 256, 256>>>();
    k_cwsl<<<(Np * 32) / 256, 256>>>(counts);
    k_final<<<1, Np>>>(out);
}

// round 6
// speedup vs baseline: 1.1174x; 1.1174x over previous
#include <cuda_runtime.h>

#define Np 1024
#define HW 4096
#define NBLK 1024       // stripe blocks
#define RPB  4          // rows per block (NBLK*RPB == HW)

// ---------------- scratch -------------------------------------------------
__device__ float    g_part[(size_t)NBLK * Np];   // 4 MB, BLK-MAJOR: [blk][box]
__device__ float    g_scores[Np];
__device__ float    g_scores_s[Np];
__device__ float    g_bbox_s[Np * 4];
__device__ unsigned g_iou[Np * 32];
__device__ float    g_rec_score[Np];
__device__ unsigned g_rec_sel[Np * 32];

// ---------------- K1: fused stripe scan + per-box row-interval sums --------
// 1024 blocks x 4 rows (round-4 structure). Partials stored blk-major float:
// warp stores are 128B-contiguous (coalesced), no sector waste.
__global__ void k_boxsum(const float4* __restrict__ p,
                         const float* __restrict__ bbox) {
    __shared__ float srow[HW];
    __shared__ float swsum[8];
    int t = threadIdx.x;            // 256
    int lane = t & 31, wid = t >> 5;
    int blk = blockIdx.x;

    int bx1[4], bx2[4], by1[4], by2[4];
    double acc[4] = {0.0, 0.0, 0.0, 0.0};
#pragma unroll
    for (int k = 0; k < 4; k++) {
        int b = t + k * 256;
        float4 bb = reinterpret_cast<const float4*>(bbox)[b];
        bx1[k] = min(max((int)floorf(bb.x), 0), HW);
        by1[k] = min(max((int)floorf(bb.y), 0), HW);
        bx2[k] = min(max((int)floorf(bb.z), 0), HW);
        by2[k] = min(max((int)floorf(bb.w), 0), HW);
    }

    int y0 = blk * RPB;
#pragma unroll
    for (int r = 0; r < RPB; r++) {
        int y = y0 + r;
        const float4* pr = p + (size_t)y * (HW / 4);
        float4 v0 = pr[t * 4 + 0], v1 = pr[t * 4 + 1];
        float4 v2 = pr[t * 4 + 2], v3 = pr[t * 4 + 3];
        v0.y += v0.x; v0.z += v0.y; v0.w += v0.z;
        v1.x += v0.w; v1.y += v1.x; v1.z += v1.y; v1.w += v1.z;
        v2.x += v1.w; v2.y += v2.x; v2.z += v2.y; v2.w += v2.z;
        v3.x += v2.w; v3.y += v3.x; v3.z += v3.y; v3.w += v3.z;
        float tot = v3.w;
        float ts = tot;
#pragma unroll
        for (int o = 1; o < 32; o <<= 1) {
            float u = __shfl_up_sync(0xffffffffu, ts, o);
            if (lane >= o) ts += u;
        }
        if (lane == 31) swsum[wid] = ts;
        __syncthreads();
        float w = 0.f;
#pragma unroll
        for (int q = 0; q < 8; q++)
            if (q < wid) w += swsum[q];
        float excl = w + (ts - tot);
        v0.x += excl; v0.y += excl; v0.z += excl; v0.w += excl;
        v1.x += excl; v1.y += excl; v1.z += excl; v1.w += excl;
        v2.x += excl; v2.y += excl; v2.z += excl; v2.w += excl;
        v3.x += excl; v3.y += excl; v3.z += excl; v3.w += excl;
        float4* sr4 = reinterpret_cast<float4*>(srow);
        sr4[t * 4 + 0] = v0; sr4[t * 4 + 1] = v1;
        sr4[t * 4 + 2] = v2; sr4[t * 4 + 3] = v3;
        __syncthreads();
#pragma unroll
        for (int k = 0; k < 4; k++) {
            if (y >= by1[k] && y < by2[k]) {
                float right = (bx2[k] > 0) ? srow[bx2[k] - 1] : 0.f;
                float left  = (bx1[k] > 0) ? srow[bx1[k] - 1] : 0.f;
                acc[k] += (double)(right - left);
            }
        }
        __syncthreads();
    }
#pragma unroll
    for (int k = 0; k < 4; k++) {
        int b = t + k * 256;
        g_part[(size_t)blk * Np + b] = (float)acc[k];   // coalesced
    }
}

// ---------------- K2: transposed reduce of partials -> combined score ------
// 128 blocks x 8 boxes. Lanes read 8-consecutive-float clusters (one 32B
// sector each); fixed-order shfl + smem reduce => deterministic.
__global__ void k_boxscore(const float* __restrict__ bbox,
                           const float* __restrict__ obj) {
    __shared__ double sw[8][8];
    int t = threadIdx.x;            // 256
    int lane = t & 31, wid = t >> 5;
    int b0 = blockIdx.x * 8;
    int boxo = lane & 7;            // box offset within group of 8
    int blko = lane >> 3;           // 0..3
    double acc = 0.0;
    int base = wid * (NBLK / 8);    // 128 blks per warp
#pragma unroll 8
    for (int it = 0; it < (NBLK / 8) / 4; it++) {
        int blk = base + it * 4 + blko;
        acc += (double)g_part[(size_t)blk * Np + b0 + boxo];
    }
    acc += __shfl_down_sync(0xffffffffu, acc, 16);
    acc += __shfl_down_sync(0xffffffffu, acc, 8);
    if (lane < 8) sw[wid][lane] = acc;
    __syncthreads();
    if (t < 8) {
        double s = 0.0;
#pragma unroll
        for (int w = 0; w < 8; w++) s += sw[w][t];
        int b = b0 + t;
        float4 bb = reinterpret_cast<const float4*>(bbox)[b];
        int x1 = min(max((int)floorf(bb.x), 0), HW);
        int y1 = min(max((int)floorf(bb.y), 0), HW);
        int x2 = min(max((int)floorf(bb.z), 0), HW);
        int y2 = min(max((int)floorf(bb.w), 0), HW);
        long long cnt = (long long)(y2 - y1) * (long long)(x2 - x1);
        if (cnt < 1) cnt = 1;
        float bs = (float)(s / (double)cnt);
        g_scores[b] = 0.5f * (obj[b] + bs);
    }
}

// ---------------- K3: rank sort (desc score, ties asc index == stable) -----
__global__ void k_sort(const float* __restrict__ bbox) {
    __shared__ float ss[Np];
    int t = threadIdx.x;  // 256
    for (int k = t; k < Np; k += 256) ss[k] = g_scores[k];
    __syncthreads();
    int i    = blockIdx.x * 8 + (t >> 5);
    int lane = t & 31;
    float si = ss[i];
    int cnt = 0;
#pragma unroll
    for (int q = 0; q < 32; q++) {
        int j = q * 32 + lane;
        float sj = ss[j];
        cnt += (sj > si) || (sj == si && j < i);
    }
#pragma unroll
    for (int o = 16; o > 0; o >>= 1) cnt += __shfl_down_sync(0xffffffffu, cnt, o);
    if (lane == 0) {
        g_scores_s[cnt] = si;
        reinterpret_cast<float4*>(g_bbox_s)[cnt] =
            reinterpret_cast<const float4*>(bbox)[i];
    }
}

// ---------------- K4: IoU > 0.5 bitmask — one warp per output word ---------
__global__ void k_iou() {
    int g    = (blockIdx.x * blockDim.x + threadIdx.x) >> 5;  // 0..32767
    int lane = threadIdx.x & 31;
    int i    = g >> 5;
    int word = g & 31;
    int j    = word * 32 + lane;
    float4 a = reinterpret_cast<const float4*>(g_bbox_s)[i];
    float4 c = reinterpret_cast<const float4*>(g_bbox_s)[j];
    float aarea = (a.z - a.x) * (a.w - a.y);
    float carea = (c.z - c.x) * (c.w - c.y);
    float ix1 = fmaxf(a.x, c.x), iy1 = fmaxf(a.y, c.y);
    float ix2 = fminf(a.z, c.z), iy2 = fminf(a.w, c.w);
    float iw = fmaxf(ix2 - ix1, 0.f), ih = fmaxf(iy2 - iy1, 0.f);
    float inter = iw * ih;
    float iou = inter / (aarea + carea - inter);
    unsigned m = __ballot_sync(0xffffffffu, iou > 0.5f);
    if (lane == 0) g_iou[i * 32 + word] = m;
}

// ---------------- K5: c_wsl greedy sweep — one warp per start (round-4) ----
__global__ void k_cwsl(const int* __restrict__ counts_p) {
    int gw   = (blockIdx.x * blockDim.x + threadIdx.x) >> 5;
    int lane = threadIdx.x & 31;
    if (gw >= Np) return;
    int counts = counts_p[0];
    int i = gw;
    unsigned sel = (lane == (i >> 5)) ? (1u << (i & 31)) : 0u;
    int   size  = 1;
    float score = g_scores_s[i];
    bool  rec   = false;
    for (int j = i + 1; j < Np; j++) {
        if (size == counts) { rec = true; break; }
        unsigned row = g_iou[j * 32 + lane];
        bool overlap = __any_sync(0xffffffffu, (sel & row) != 0u);
        if (!overlap) {
            if (lane == (j >> 5)) sel |= (1u << (j & 31));
            size++;
            score += g_scores_s[j];
        }
    }
    g_rec_sel[i * 32 + lane] = sel;
    if (lane == 0) g_rec_score[i] = rec ? score : -1e30f;
}

// ---------------- K6: last-argmax over recorded scores + emit output -------
__global__ void k_final(float* __restrict__ out) {
    __shared__ float ss[Np];
    __shared__ int   si[Np];
    int t = threadIdx.x;
    ss[t] = g_rec_score[t];
    si[t] = t;
    __syncthreads();
    for (int s = Np / 2; s > 0; s >>= 1) {
        if (t < s) {
            float o = ss[t + s]; int oi = si[t + s];
            if (o > ss[t] || (o == ss[t] && oi > si[t])) { ss[t] = o; si[t] = oi; }
        }
        __syncthreads();
    }
    __shared__ int bestIdx, anyrec;
    if (t == 0) { bestIdx = si[0]; anyrec = (ss[0] > -1e29f) ? 1 : 0; }
    __syncthreads();
    unsigned bit = (g_rec_sel[bestIdx * 32 + (t >> 5)] >> (t & 31)) & 1u;
    out[t] = (anyrec && bit) ? g_scores_s[t] : 0.f;
}

// ---------------- launch ----------------------------------------------------
extern "C" void kernel_launch(void* const* d_in, const int* in_sizes, int n_in,
                              void* d_out, int out_size) {
    const float* bbox   = (const float*)d_in[0];
    const float* obj    = (const float*)d_in[1];
    const float* probs  = (const float*)d_in[2];
    const int*   counts = (const int*)d_in[3];
    float* out = (float*)d_out;

    k_boxsum<<<NBLK, 256>>>((const float4*)probs, bbox);
    k_boxscore<<<Np / 8, 256>>>(bbox, obj);
    k_sort<<<Np / 8, 256>>>(bbox);
    k_iou<<<(Np * 32 * 32) / 256, 256>>>();
    k_cwsl<<<(Np * 32) / 256, 256>>>(counts);
    k_final<<<1, Np>>>(out);
}